// round 2
// baseline (speedup 1.0000x reference)
#include <cuda_runtime.h>
#include <cstdint>

#define BDIM 4
#define SDIM 2048
#define HDIM 1024
#define NH   16
#define DH   64
#define QT   16
#define KT   128

// Scratch (device globals: no allocation allowed in kernel_launch)
__device__ float g_Q[(size_t)BDIM * NH * SDIM * DH];
__device__ float g_K[(size_t)BDIM * NH * SDIM * DH];
__device__ float g_V[(size_t)BDIM * NH * SDIM * DH];
__device__ float g_ctx[(size_t)BDIM * SDIM * HDIM];

// ---------------------------------------------------------------------------
// C[M,N] = A[M,K] @ W[N,K]^T + bias ;  optional scatter to [B,H,S,Dh] layout
// 128x128 tile, BK=8, 256 threads, 8x8 register tile per thread.
// ---------------------------------------------------------------------------
template <bool SPLIT>
__global__ void __launch_bounds__(256) sgemm_bias(
    const float* __restrict__ A, const float* __restrict__ W,
    const float* __restrict__ bias, float* __restrict__ C,
    int M, int N, int K)
{
    __shared__ __align__(16) float As[8][128];
    __shared__ __align__(16) float Bs[8][128];

    const int tid  = threadIdx.x;
    const int brow = blockIdx.y * 128;
    const int bcol = blockIdx.x * 128;
    const int lrow = tid >> 1;            // 0..127
    const int lcol = (tid & 1) * 4;       // 0 or 4
    const int tr   = tid >> 4;            // 0..15
    const int tc   = tid & 15;            // 0..15

    float acc[8][8];
#pragma unroll
    for (int i = 0; i < 8; i++)
#pragma unroll
        for (int j = 0; j < 8; j++) acc[i][j] = 0.f;

    const float* Ap = A + (size_t)(brow + lrow) * K + lcol;
    const float* Wp = W + (size_t)(bcol + lrow) * K + lcol;

    for (int k0 = 0; k0 < K; k0 += 8) {
        float4 a4 = *(const float4*)(Ap + k0);
        float4 b4 = *(const float4*)(Wp + k0);
        As[lcol + 0][lrow] = a4.x; As[lcol + 1][lrow] = a4.y;
        As[lcol + 2][lrow] = a4.z; As[lcol + 3][lrow] = a4.w;
        Bs[lcol + 0][lrow] = b4.x; Bs[lcol + 1][lrow] = b4.y;
        Bs[lcol + 2][lrow] = b4.z; Bs[lcol + 3][lrow] = b4.w;
        __syncthreads();
#pragma unroll
        for (int k = 0; k < 8; k++) {
            float4 a0 = *(const float4*)&As[k][tr * 8];
            float4 a1 = *(const float4*)&As[k][tr * 8 + 4];
            float4 b0 = *(const float4*)&Bs[k][tc * 8];
            float4 b1 = *(const float4*)&Bs[k][tc * 8 + 4];
            float af[8] = {a0.x, a0.y, a0.z, a0.w, a1.x, a1.y, a1.z, a1.w};
            float bf[8] = {b0.x, b0.y, b0.z, b0.w, b1.x, b1.y, b1.z, b1.w};
#pragma unroll
            for (int i = 0; i < 8; i++)
#pragma unroll
                for (int j = 0; j < 8; j++) acc[i][j] += af[i] * bf[j];
        }
        __syncthreads();
    }

#pragma unroll
    for (int i = 0; i < 8; i++) {
        const int row = brow + tr * 8 + i;
#pragma unroll
        for (int j = 0; j < 8; j++) {
            const int col = bcol + tc * 8 + j;
            const float v = acc[i][j] + bias[col];
            if (SPLIT) {
                const int b = row / SDIM, s = row % SDIM;
                const int h = col / DH,  d = col % DH;
                C[(((size_t)(b * NH + h)) * SDIM + s) * DH + d] = v;
            } else {
                C[(size_t)row * N + col] = v;
            }
        }
    }
}

// ---------------------------------------------------------------------------
// Fused attention: per (b, h, 16-query tile):
//   scores (full row in smem) -> softmax -> write attention -> PV -> ctx
// 512 threads; warp w owns query row w of the tile.
// ---------------------------------------------------------------------------
__global__ void __launch_bounds__(512) attn_kernel(
    const int* __restrict__ mask, float* __restrict__ att)
{
    extern __shared__ float sm[];
    float* Ss  = sm;                    // QT * SDIM floats   (scores / probs)
    float* KVs = Ss + QT * SDIM;        // KT * 65 floats     (K or V tile, padded)
    float* Qs  = KVs + KT * 65;         // QT * DH floats
    int*   Ms  = (int*)(Qs + QT * DH);  // SDIM ints          (mask row)

    const int tid  = threadIdx.x;
    const int q0   = blockIdx.x * QT;
    const int h    = blockIdx.y;
    const int b    = blockIdx.z;
    const int bh   = b * NH + h;
    const int wid  = tid >> 5;
    const int lane = tid & 31;

    const float* Qg = g_Q + ((size_t)bh * SDIM + q0) * DH;
    const float* Kg = g_K + (size_t)bh * SDIM * DH;
    const float* Vg = g_V + (size_t)bh * SDIM * DH;

    for (int i = tid; i < QT * DH; i += 512) Qs[i] = Qg[i];
    for (int i = tid; i < SDIM; i += 512)    Ms[i] = mask[b * SDIM + i];

    const int kr = tid >> 2;          // 0..127 : tile row to load
    const int kd = (tid & 3) * 16;    // 16-float chunk within row

    // ---- Phase 1: scores ----
    for (int kt = 0; kt < SDIM / KT; kt++) {
        __syncthreads();  // KVs free; also covers Qs/Ms loads on first iter
        {
            const float* src = Kg + (size_t)(kt * KT + kr) * DH + kd;
            float* dst = &KVs[kr * 65 + kd];
#pragma unroll
            for (int r = 0; r < 4; r++) {
                float4 v = *(const float4*)(src + 4 * r);
                dst[4 * r + 0] = v.x; dst[4 * r + 1] = v.y;
                dst[4 * r + 2] = v.z; dst[4 * r + 3] = v.w;
            }
        }
        __syncthreads();

        float a0 = 0.f, a1 = 0.f, a2 = 0.f, a3 = 0.f;
#pragma unroll 16
        for (int d = 0; d < DH; d++) {
            const float qv = Qs[wid * DH + d];
            a0 += qv * KVs[(lane     ) * 65 + d];
            a1 += qv * KVs[(lane + 32) * 65 + d];
            a2 += qv * KVs[(lane + 64) * 65 + d];
            a3 += qv * KVs[(lane + 96) * 65 + d];
        }
        const int kb = kt * KT;
        float s0 = a0 * 0.125f, s1 = a1 * 0.125f;
        float s2 = a2 * 0.125f, s3 = a3 * 0.125f;
        if (Ms[kb + lane     ] == 0) s0 = -1e10f;
        if (Ms[kb + lane + 32] == 0) s1 = -1e10f;
        if (Ms[kb + lane + 64] == 0) s2 = -1e10f;
        if (Ms[kb + lane + 96] == 0) s3 = -1e10f;
        float* srow = Ss + wid * SDIM + kb;
        srow[lane] = s0; srow[lane + 32] = s1;
        srow[lane + 64] = s2; srow[lane + 96] = s3;
    }
    __syncthreads();

    // ---- Phase 2: softmax over own row (one warp per query row) ----
    {
        float* row = Ss + wid * SDIM;
        float m = -3.4e38f;
        for (int i = lane; i < SDIM; i += 32) m = fmaxf(m, row[i]);
#pragma unroll
        for (int o = 16; o > 0; o >>= 1) m = fmaxf(m, __shfl_xor_sync(0xffffffffu, m, o));
        float ssum = 0.f;
        for (int i = lane; i < SDIM; i += 32) {
            const float e = __expf(row[i] - m);
            row[i] = e;
            ssum += e;
        }
#pragma unroll
        for (int o = 16; o > 0; o >>= 1) ssum += __shfl_xor_sync(0xffffffffu, ssum, o);
        const float inv = 1.f / ssum;
        float* arow = att ? att + ((size_t)bh * SDIM + q0 + wid) * SDIM : nullptr;
        for (int i = lane; i < SDIM; i += 32) {
            const float p = row[i] * inv;
            row[i] = p;
            if (arow) arow[i] = p;
        }
    }

    // ---- Phase 3: PV (each warp: its query row; lane covers d and d+32) ----
    float o0 = 0.f, o1 = 0.f;
    for (int kt = 0; kt < SDIM / KT; kt++) {
        __syncthreads();  // KVs free (all warps past phase-1 reads)
        {
            const float* src = Vg + (size_t)(kt * KT + kr) * DH + kd;
            float* dst = &KVs[kr * 65 + kd];
#pragma unroll
            for (int r = 0; r < 4; r++) {
                float4 v = *(const float4*)(src + 4 * r);
                dst[4 * r + 0] = v.x; dst[4 * r + 1] = v.y;
                dst[4 * r + 2] = v.z; dst[4 * r + 3] = v.w;
            }
        }
        __syncthreads();
        const float* prow = Ss + wid * SDIM + kt * KT;
#pragma unroll 8
        for (int k = 0; k < KT; k++) {
            const float p = prow[k];
            o0 += p * KVs[k * 65 + lane];
            o1 += p * KVs[k * 65 + 32 + lane];
        }
    }
    float* crow = g_ctx + ((size_t)(b * SDIM + q0 + wid)) * HDIM + h * DH;
    crow[lane]      = o0;
    crow[lane + 32] = o1;
}

// ---------------------------------------------------------------------------
extern "C" void kernel_launch(void* const* d_in, const int* in_sizes, int n_in,
                              void* d_out, int out_size)
{
    const float* query  = (const float*)d_in[0];
    const float* key_in = (const float*)d_in[1];
    const float* value  = (const float*)d_in[2];
    const int*   mask   = (const int*)  d_in[3];
    const float* Wq = (const float*)d_in[4],  *bq = (const float*)d_in[5];
    const float* Wk = (const float*)d_in[6],  *bk = (const float*)d_in[7];
    const float* Wv = (const float*)d_in[8],  *bv = (const float*)d_in[9];
    const float* Wo = (const float*)d_in[10], *bo = (const float*)d_in[11];
    float* out = (float*)d_out;

    float *qbuf, *kbuf, *vbuf, *cbuf;
    cudaGetSymbolAddress((void**)&qbuf, g_Q);
    cudaGetSymbolAddress((void**)&kbuf, g_K);
    cudaGetSymbolAddress((void**)&vbuf, g_V);
    cudaGetSymbolAddress((void**)&cbuf, g_ctx);

    const long long XE = (long long)BDIM * SDIM * HDIM;          // 8,388,608
    const long long AE = (long long)BDIM * NH * SDIM * SDIM;     // 268,435,456
    float* att = ((long long)out_size >= XE + AE) ? out + XE : nullptr;

    const dim3 gg(HDIM / 128, (BDIM * SDIM) / 128);
    sgemm_bias<true><<<gg, 256>>>(query,  Wq, bq, qbuf, BDIM * SDIM, HDIM, HDIM);
    sgemm_bias<true><<<gg, 256>>>(key_in, Wk, bk, kbuf, BDIM * SDIM, HDIM, HDIM);
    sgemm_bias<true><<<gg, 256>>>(value,  Wv, bv, vbuf, BDIM * SDIM, HDIM, HDIM);

    const size_t smem = (QT * SDIM + KT * 65 + QT * DH) * sizeof(float)
                      + SDIM * sizeof(int);
    cudaFuncSetAttribute(attn_kernel, cudaFuncAttributeMaxDynamicSharedMemorySize,
                         (int)smem);
    attn_kernel<<<dim3(SDIM / QT, NH, BDIM), 512, smem>>>(mask, att);

    sgemm_bias<false><<<gg, 256>>>(cbuf, Wo, bo, out, BDIM * SDIM, HDIM, HDIM);
}

// round 3
// speedup vs baseline: 3.6960x; 3.6960x over previous
#include <cuda_runtime.h>
#include <cstdint>

#define BDIM 4
#define SDIM 2048
#define HDIM 1024
#define NH   16
#define DH   64

// Scratch (device globals: no allocation allowed in kernel_launch)
__device__ float g_Q[(size_t)BDIM * NH * SDIM * DH];
__device__ float g_K[(size_t)BDIM * NH * SDIM * DH];
__device__ float g_V[(size_t)BDIM * NH * SDIM * DH];
__device__ float g_ctx[(size_t)BDIM * SDIM * HDIM];

// ---------------------------------------------------------------------------
// Helpers
// ---------------------------------------------------------------------------
__device__ __forceinline__ float to_tf32(float x) {
    float r;
    asm("cvt.rna.tf32.f32 %0, %1;" : "=f"(r) : "f"(x));
    return r;
}

__device__ __forceinline__ void mma_tf32(float* c, const unsigned* a,
                                         const unsigned* b) {
    asm volatile(
        "mma.sync.aligned.m16n8k8.row.col.f32.tf32.tf32.f32 "
        "{%0,%1,%2,%3}, {%4,%5,%6,%7}, {%8,%9}, {%0,%1,%2,%3};\n"
        : "+f"(c[0]), "+f"(c[1]), "+f"(c[2]), "+f"(c[3])
        : "r"(a[0]), "r"(a[1]), "r"(a[2]), "r"(a[3]), "r"(b[0]), "r"(b[1]));
}

// ---------------------------------------------------------------------------
// C[M,N] = alpha * A[M,K] @ B[N,K]^T (+ bias)
// MODE 0: direct row-major C (ldc = N), optional bias
// MODE 1: scatter to [B,H,S,Dh] (proj output), optional bias
// MODE 2: batched direct (blockIdx.z batches via strides), bias unused
// Tile 128x128, BK=32, 256 threads, 8 warps (2x4), warp tile 64x32.
// ---------------------------------------------------------------------------
template <int MODE>
__global__ void __launch_bounds__(256) gemm_abt(
    const float* __restrict__ A, const float* __restrict__ Bm,
    const float* __restrict__ bias, float* __restrict__ C,
    int M, int N, int K,
    long long sA, long long sB, long long sC, float alpha)
{
    __shared__ float As[128][36];
    __shared__ float Bs[128][36];

    const int z = blockIdx.z;
    A  += (size_t)z * sA;
    Bm += (size_t)z * sB;
    C  += (size_t)z * sC;

    const int tid  = threadIdx.x;
    const int wid  = tid >> 5, lane = tid & 31;
    const int wm   = wid >> 2, wn = wid & 3;     // warp grid 2(m) x 4(n)
    const int g    = lane >> 2, qd = lane & 3;   // octet-group, quad

    const int brow = blockIdx.y * 128;
    const int bcol = blockIdx.x * 128;

    const int lr = tid >> 3;         // 0..31 (rows lr + i*32)
    const int lk = (tid & 7) * 4;    // k offset within chunk

    float acc[4][4][4];
#pragma unroll
    for (int i = 0; i < 4; i++)
#pragma unroll
        for (int j = 0; j < 4; j++)
#pragma unroll
            for (int r = 0; r < 4; r++) acc[i][j][r] = 0.f;

    float4 pa[4], pb[4];

    // prefetch tile 0
#pragma unroll
    for (int i = 0; i < 4; i++) {
        pa[i] = *(const float4*)(A  + (size_t)(brow + lr + i * 32) * K + lk);
        pb[i] = *(const float4*)(Bm + (size_t)(bcol + lr + i * 32) * K + lk);
    }

    for (int k0 = 0; k0 < K; k0 += 32) {
        // store staged tile to smem (tf32-rounded)
#pragma unroll
        for (int i = 0; i < 4; i++) {
            *(float4*)&As[lr + i * 32][lk] = make_float4(
                to_tf32(pa[i].x), to_tf32(pa[i].y), to_tf32(pa[i].z), to_tf32(pa[i].w));
            *(float4*)&Bs[lr + i * 32][lk] = make_float4(
                to_tf32(pb[i].x), to_tf32(pb[i].y), to_tf32(pb[i].z), to_tf32(pb[i].w));
        }
        __syncthreads();

        const bool more = (k0 + 32) < K;
        if (more) {
#pragma unroll
            for (int i = 0; i < 4; i++) {
                pa[i] = *(const float4*)(A  + (size_t)(brow + lr + i * 32) * K + k0 + 32 + lk);
                pb[i] = *(const float4*)(Bm + (size_t)(bcol + lr + i * 32) * K + k0 + 32 + lk);
            }
        }

#pragma unroll
        for (int ks = 0; ks < 4; ks++) {
            const int kb = ks * 8;
            unsigned a[4][4], b[4][2];
#pragma unroll
            for (int mt = 0; mt < 4; mt++) {
                const int r0 = wm * 64 + mt * 16 + g;
                a[mt][0] = __float_as_uint(As[r0    ][kb + qd]);
                a[mt][1] = __float_as_uint(As[r0 + 8][kb + qd]);
                a[mt][2] = __float_as_uint(As[r0    ][kb + qd + 4]);
                a[mt][3] = __float_as_uint(As[r0 + 8][kb + qd + 4]);
            }
#pragma unroll
            for (int nt = 0; nt < 4; nt++) {
                const int c0 = wn * 32 + nt * 8 + g;
                b[nt][0] = __float_as_uint(Bs[c0][kb + qd]);
                b[nt][1] = __float_as_uint(Bs[c0][kb + qd + 4]);
            }
#pragma unroll
            for (int mt = 0; mt < 4; mt++)
#pragma unroll
                for (int nt = 0; nt < 4; nt++)
                    mma_tf32(acc[mt][nt], a[mt], b[nt]);
        }
        __syncthreads();
    }

    // epilogue
#pragma unroll
    for (int mt = 0; mt < 4; mt++) {
#pragma unroll
        for (int nt = 0; nt < 4; nt++) {
            const int cc = bcol + wn * 32 + nt * 8 + 2 * qd;
            float bx = 0.f, by = 0.f;
            if (MODE != 2 && bias) { bx = bias[cc]; by = bias[cc + 1]; }
#pragma unroll
            for (int half = 0; half < 2; half++) {
                const int r = brow + wm * 64 + mt * 16 + g + half * 8;
                float2 v;
                v.x = alpha * acc[mt][nt][2 * half]     + bx;
                v.y = alpha * acc[mt][nt][2 * half + 1] + by;
                if (MODE == 1) {
                    const int b_ = r / SDIM, s = r % SDIM;
                    const int h  = cc / DH,  d = cc % DH;
                    *(float2*)&C[(((size_t)(b_ * NH + h)) * SDIM + s) * DH + d] = v;
                } else {
                    *(float2*)&C[(size_t)r * N + cc] = v;
                }
            }
        }
    }
}

// ---------------------------------------------------------------------------
// PV: per batch bh:  ctx_part[2048,64] = P[2048,2048] @ V[2048,64]
// Tile 128(m) x 64(n), BK=32. 256 threads, 8 warps (4x2), warp tile 32x32.
// Output scattered into g_ctx [B, S, HID].
// ---------------------------------------------------------------------------
__global__ void __launch_bounds__(256) gemm_pv(
    const float* __restrict__ P, float* __restrict__ ctx)
{
    __shared__ float As[128][36];
    __shared__ float Bs[32][72];

    const int bh = blockIdx.y;
    const float* A  = P + (size_t)bh * SDIM * SDIM;
    const float* Vg = g_V + (size_t)bh * SDIM * DH;

    const int tid  = threadIdx.x;
    const int wid  = tid >> 5, lane = tid & 31;
    const int wm   = wid >> 1, wn = wid & 1;     // warp grid 4(m) x 2(n)
    const int g    = lane >> 2, qd = lane & 3;

    const int brow = blockIdx.x * 128;

    const int lr = tid >> 3;         // P tile rows
    const int lk = (tid & 7) * 4;
    const int vr = tid >> 4;         // V tile rows (0..15, + 16)
    const int vc = (tid & 15) * 4;

    float acc[2][4][4];
#pragma unroll
    for (int i = 0; i < 2; i++)
#pragma unroll
        for (int j = 0; j < 4; j++)
#pragma unroll
            for (int r = 0; r < 4; r++) acc[i][j][r] = 0.f;

    float4 pa[4], pv[2];
#pragma unroll
    for (int i = 0; i < 4; i++)
        pa[i] = *(const float4*)(A + (size_t)(brow + lr + i * 32) * SDIM + lk);
#pragma unroll
    for (int i = 0; i < 2; i++)
        pv[i] = *(const float4*)(Vg + (size_t)(vr + i * 16) * DH + vc);

    for (int k0 = 0; k0 < SDIM; k0 += 32) {
#pragma unroll
        for (int i = 0; i < 4; i++)
            *(float4*)&As[lr + i * 32][lk] = make_float4(
                to_tf32(pa[i].x), to_tf32(pa[i].y), to_tf32(pa[i].z), to_tf32(pa[i].w));
#pragma unroll
        for (int i = 0; i < 2; i++)
            *(float4*)&Bs[vr + i * 16][vc] = make_float4(
                to_tf32(pv[i].x), to_tf32(pv[i].y), to_tf32(pv[i].z), to_tf32(pv[i].w));
        __syncthreads();

        const bool more = (k0 + 32) < SDIM;
        if (more) {
#pragma unroll
            for (int i = 0; i < 4; i++)
                pa[i] = *(const float4*)(A + (size_t)(brow + lr + i * 32) * SDIM + k0 + 32 + lk);
#pragma unroll
            for (int i = 0; i < 2; i++)
                pv[i] = *(const float4*)(Vg + (size_t)(k0 + 32 + vr + i * 16) * DH + vc);
        }

#pragma unroll
        for (int ks = 0; ks < 4; ks++) {
            const int kb = ks * 8;
            unsigned a[2][4], b[4][2];
#pragma unroll
            for (int mt = 0; mt < 2; mt++) {
                const int r0 = wm * 32 + mt * 16 + g;
                a[mt][0] = __float_as_uint(As[r0    ][kb + qd]);
                a[mt][1] = __float_as_uint(As[r0 + 8][kb + qd]);
                a[mt][2] = __float_as_uint(As[r0    ][kb + qd + 4]);
                a[mt][3] = __float_as_uint(As[r0 + 8][kb + qd + 4]);
            }
#pragma unroll
            for (int nt = 0; nt < 4; nt++) {
                const int c0 = wn * 32 + nt * 8 + g;
                b[nt][0] = __float_as_uint(Bs[kb + qd    ][c0]);
                b[nt][1] = __float_as_uint(Bs[kb + qd + 4][c0]);
            }
#pragma unroll
            for (int mt = 0; mt < 2; mt++)
#pragma unroll
                for (int nt = 0; nt < 4; nt++)
                    mma_tf32(acc[mt][nt], a[mt], b[nt]);
        }
        __syncthreads();
    }

    const int b_ = bh / NH, h = bh % NH;
#pragma unroll
    for (int mt = 0; mt < 2; mt++) {
#pragma unroll
        for (int nt = 0; nt < 4; nt++) {
            const int d = wn * 32 + nt * 8 + 2 * qd;
#pragma unroll
            for (int half = 0; half < 2; half++) {
                const int s = brow + wm * 32 + mt * 16 + g + half * 8;
                float2 v;
                v.x = acc[mt][nt][2 * half];
                v.y = acc[mt][nt][2 * half + 1];
                *(float2*)&ctx[((size_t)(b_ * SDIM + s)) * HDIM + h * DH + d] = v;
            }
        }
    }
}

// ---------------------------------------------------------------------------
// In-place masked softmax over the last dim of att [B*H*S, S].
// 8 warps per block, one warp per row; row cached in registers (64 f/lane).
// ---------------------------------------------------------------------------
__global__ void __launch_bounds__(256) softmax_rows(
    float* __restrict__ att, const int* __restrict__ mask)
{
    const int wid  = threadIdx.x >> 5;
    const int lane = threadIdx.x & 31;
    const long long row = (long long)blockIdx.x * 8 + wid;

    float* rp = att + (size_t)row * SDIM;
    const int b_ = (int)(row / ((long long)NH * SDIM));
    const int4* mrow = (const int4*)(mask + b_ * SDIM);
    const float4* rp4 = (const float4*)rp;

    float v[64];
    float m = -3.4e38f;
#pragma unroll
    for (int j = 0; j < 16; j++) {
        float4 x = rp4[lane + j * 32];
        int4 mm  = mrow[lane + j * 32];
        if (mm.x == 0) x.x = -1e10f;
        if (mm.y == 0) x.y = -1e10f;
        if (mm.z == 0) x.z = -1e10f;
        if (mm.w == 0) x.w = -1e10f;
        v[4 * j + 0] = x.x; v[4 * j + 1] = x.y;
        v[4 * j + 2] = x.z; v[4 * j + 3] = x.w;
        m = fmaxf(m, fmaxf(fmaxf(x.x, x.y), fmaxf(x.z, x.w)));
    }
#pragma unroll
    for (int o = 16; o > 0; o >>= 1) m = fmaxf(m, __shfl_xor_sync(0xffffffffu, m, o));

    float s = 0.f;
#pragma unroll
    for (int i = 0; i < 64; i++) {
        v[i] = __expf(v[i] - m);
        s += v[i];
    }
#pragma unroll
    for (int o = 16; o > 0; o >>= 1) s += __shfl_xor_sync(0xffffffffu, s, o);
    const float inv = 1.f / s;

    float4* wp4 = (float4*)rp;
#pragma unroll
    for (int j = 0; j < 16; j++) {
        float4 x;
        x.x = v[4 * j + 0] * inv; x.y = v[4 * j + 1] * inv;
        x.z = v[4 * j + 2] * inv; x.w = v[4 * j + 3] * inv;
        wp4[lane + j * 32] = x;
    }
}

// ---------------------------------------------------------------------------
extern "C" void kernel_launch(void* const* d_in, const int* in_sizes, int n_in,
                              void* d_out, int out_size)
{
    const float* query  = (const float*)d_in[0];
    const float* key_in = (const float*)d_in[1];
    const float* value  = (const float*)d_in[2];
    const int*   mask   = (const int*)  d_in[3];
    const float* Wq = (const float*)d_in[4],  *bq = (const float*)d_in[5];
    const float* Wk = (const float*)d_in[6],  *bk = (const float*)d_in[7];
    const float* Wv = (const float*)d_in[8],  *bv = (const float*)d_in[9];
    const float* Wo = (const float*)d_in[10], *bo = (const float*)d_in[11];
    float* out = (float*)d_out;

    float *qbuf, *kbuf, *vbuf, *cbuf;
    cudaGetSymbolAddress((void**)&qbuf, g_Q);
    cudaGetSymbolAddress((void**)&kbuf, g_K);
    cudaGetSymbolAddress((void**)&vbuf, g_V);
    cudaGetSymbolAddress((void**)&cbuf, g_ctx);

    const long long XE = (long long)BDIM * SDIM * HDIM;       // 8,388,608
    float* att = out + XE;                                    // [B,H,S,S]

    // 1) QKV projections (tf32 MMA), scatter to [B,H,S,Dh]
    const dim3 gp(HDIM / 128, (BDIM * SDIM) / 128, 1);
    gemm_abt<1><<<gp, 256>>>(query,  Wq, bq, qbuf, BDIM * SDIM, HDIM, HDIM, 0, 0, 0, 1.f);
    gemm_abt<1><<<gp, 256>>>(key_in, Wk, bk, kbuf, BDIM * SDIM, HDIM, HDIM, 0, 0, 0, 1.f);
    gemm_abt<1><<<gp, 256>>>(value,  Wv, bv, vbuf, BDIM * SDIM, HDIM, HDIM, 0, 0, 0, 1.f);

    // 2) Scores: per (b,h)  E = Q @ K^T / 8   -> att region (energies)
    const long long hd = (long long)SDIM * DH;
    const long long ss = (long long)SDIM * SDIM;
    gemm_abt<2><<<dim3(SDIM / 128, SDIM / 128, BDIM * NH), 256>>>(
        qbuf, kbuf, nullptr, att, SDIM, SDIM, DH, hd, hd, ss, 0.125f);

    // 3) Softmax (mask + normalize) in place -> attention probs (2nd output)
    softmax_rows<<<(BDIM * NH * SDIM) / 8, 256>>>(att, mask);

    // 4) PV: ctx[b,s,h*64+d] = sum_k P V
    gemm_pv<<<dim3(SDIM / 128, BDIM * NH), 256>>>(att, cbuf);

    // 5) Output projection -> x (1st output)
    gemm_abt<0><<<gp, 256>>>(cbuf, Wo, bo, out, BDIM * SDIM, HDIM, HDIM, 0, 0, 0, 1.f);
}

// round 4
// speedup vs baseline: 4.7646x; 1.2891x over previous
#include <cuda_runtime.h>
#include <cstdint>

#define BDIM 4
#define SDIM 2048
#define HDIM 1024
#define NH   16
#define DH   64

#define MB 256
#define NB 128
#define KB 16
#define PMB 512

// Scratch (device globals: no allocation allowed in kernel_launch)
__device__ float g_Q[(size_t)BDIM * NH * SDIM * DH];
__device__ float g_K[(size_t)BDIM * NH * SDIM * DH];
__device__ float g_V[(size_t)BDIM * NH * SDIM * DH];
__device__ float g_ctx[(size_t)BDIM * SDIM * HDIM];

// ---------------------------------------------------------------------------
__device__ __forceinline__ float to_tf32(float x) {
    float r;
    asm("cvt.rna.tf32.f32 %0, %1;" : "=f"(r) : "f"(x));
    return r;
}
__device__ __forceinline__ float4 tf32x4(float4 v) {
    return make_float4(to_tf32(v.x), to_tf32(v.y), to_tf32(v.z), to_tf32(v.w));
}
__device__ __forceinline__ void mma_tf32(float* c, const unsigned* a,
                                         const unsigned* b) {
    asm volatile(
        "mma.sync.aligned.m16n8k8.row.col.f32.tf32.tf32.f32 "
        "{%0,%1,%2,%3}, {%4,%5,%6,%7}, {%8,%9}, {%0,%1,%2,%3};\n"
        : "+f"(c[0]), "+f"(c[1]), "+f"(c[2]), "+f"(c[3])
        : "r"(a[0]), "r"(a[1]), "r"(a[2]), "r"(a[3]), "r"(b[0]), "r"(b[1]));
}

// ---------------------------------------------------------------------------
// C[M,N] = alpha * A[M,K] @ B[N,K]^T (+ bias)
// MODE 0: direct row-major C (ldc), + bias
// MODE 1: scatter to [B,H,S,Dh], + bias
// MODE 2: batched direct via strides (z), no bias
// Block tile 256x128, BK=16, 256 threads, 8 warps (4m x 2n), warp tile 64x64.
// ---------------------------------------------------------------------------
template <int MODE>
__global__ void __launch_bounds__(256, 1) gemm64(
    const float* __restrict__ A, const float* __restrict__ Bm,
    const float* __restrict__ bias, float* __restrict__ C,
    int K, int ldc, long long sA, long long sB, long long sC, float alpha)
{
    __shared__ float As[MB][20];
    __shared__ float Bs[NB][20];

    const int z = blockIdx.z;
    A  += (size_t)z * sA;
    Bm += (size_t)z * sB;
    C  += (size_t)z * sC;

    const int tid  = threadIdx.x;
    const int wid  = tid >> 5, lane = tid & 31;
    const int wm   = wid >> 1, wn = wid & 1;
    const int g    = lane >> 2, qd = lane & 3;
    const int brow = blockIdx.y * MB;
    const int bcol = blockIdx.x * NB;

    const int lr = tid >> 2;        // 0..63
    const int lc = (tid & 3) * 4;   // 0,4,8,12

    float acc[4][8][4];
#pragma unroll
    for (int i = 0; i < 4; i++)
#pragma unroll
        for (int j = 0; j < 8; j++)
#pragma unroll
            for (int r = 0; r < 4; r++) acc[i][j][r] = 0.f;

    float4 pa[4], pb[2];
#pragma unroll
    for (int p = 0; p < 4; p++)
        pa[p] = *(const float4*)(A + (size_t)(brow + lr + 64 * p) * K + lc);
#pragma unroll
    for (int p = 0; p < 2; p++)
        pb[p] = *(const float4*)(Bm + (size_t)(bcol + lr + 64 * p) * K + lc);

    for (int k0 = 0; k0 < K; k0 += KB) {
#pragma unroll
        for (int p = 0; p < 4; p++)
            *(float4*)&As[lr + 64 * p][lc] = tf32x4(pa[p]);
#pragma unroll
        for (int p = 0; p < 2; p++)
            *(float4*)&Bs[lr + 64 * p][lc] = tf32x4(pb[p]);
        __syncthreads();

        if (k0 + KB < K) {
#pragma unroll
            for (int p = 0; p < 4; p++)
                pa[p] = *(const float4*)(A + (size_t)(brow + lr + 64 * p) * K + k0 + KB + lc);
#pragma unroll
            for (int p = 0; p < 2; p++)
                pb[p] = *(const float4*)(Bm + (size_t)(bcol + lr + 64 * p) * K + k0 + KB + lc);
        }

#pragma unroll
        for (int ks = 0; ks < 2; ks++) {
            const int kb = ks * 8;
            unsigned a[4][4], b[8][2];
#pragma unroll
            for (int mt = 0; mt < 4; mt++) {
                const int r0 = wm * 64 + mt * 16 + g;
                a[mt][0] = __float_as_uint(As[r0    ][kb + qd]);
                a[mt][1] = __float_as_uint(As[r0 + 8][kb + qd]);
                a[mt][2] = __float_as_uint(As[r0    ][kb + qd + 4]);
                a[mt][3] = __float_as_uint(As[r0 + 8][kb + qd + 4]);
            }
#pragma unroll
            for (int nt = 0; nt < 8; nt++) {
                const int c0 = wn * 64 + nt * 8 + g;
                b[nt][0] = __float_as_uint(Bs[c0][kb + qd]);
                b[nt][1] = __float_as_uint(Bs[c0][kb + qd + 4]);
            }
#pragma unroll
            for (int mt = 0; mt < 4; mt++)
#pragma unroll
                for (int nt = 0; nt < 8; nt++)
                    mma_tf32(acc[mt][nt], a[mt], b[nt]);
        }
        __syncthreads();
    }

#pragma unroll
    for (int mt = 0; mt < 4; mt++) {
#pragma unroll
        for (int nt = 0; nt < 8; nt++) {
            const int cc = bcol + wn * 64 + nt * 8 + 2 * qd;
            float bx = 0.f, by = 0.f;
            if (MODE != 2) { bx = bias[cc]; by = bias[cc + 1]; }
#pragma unroll
            for (int half = 0; half < 2; half++) {
                const int r = brow + wm * 64 + mt * 16 + g + half * 8;
                float2 v;
                v.x = alpha * acc[mt][nt][2 * half]     + bx;
                v.y = alpha * acc[mt][nt][2 * half + 1] + by;
                if (MODE == 1) {
                    const int b_ = r / SDIM, s = r % SDIM;
                    const int h  = cc / DH,  d = cc % DH;
                    *(float2*)&C[(((size_t)(b_ * NH + h)) * SDIM + s) * DH + d] = v;
                } else {
                    *(float2*)&C[(size_t)r * ldc + cc] = v;
                }
            }
        }
    }
}

// ---------------------------------------------------------------------------
// PV: per (b,h): ctx_part[2048,64] = P[2048,2048] @ V[2048,64]
// Block tile 512x64, BK=16, 256 threads, 8 m-stacked warps, warp tile 64x64.
// ---------------------------------------------------------------------------
__global__ void __launch_bounds__(256, 1) gemm_pv64(
    const float* __restrict__ P, float* __restrict__ ctx)
{
    __shared__ float As[PMB][20];
    __shared__ float Vs[16][72];

    const int bh = blockIdx.y;
    const float* A  = P + (size_t)bh * SDIM * SDIM;
    const float* Vg = g_V + (size_t)bh * SDIM * DH;

    const int tid  = threadIdx.x;
    const int wid  = tid >> 5, lane = tid & 31;
    const int g    = lane >> 2, qd = lane & 3;
    const int brow = blockIdx.x * PMB;

    const int lr = tid >> 2;        // 0..63
    const int lc = (tid & 3) * 4;
    const int vr = tid >> 4;        // 0..15
    const int vc = (tid & 15) * 4;  // 0..60

    float acc[4][8][4];
#pragma unroll
    for (int i = 0; i < 4; i++)
#pragma unroll
        for (int j = 0; j < 8; j++)
#pragma unroll
            for (int r = 0; r < 4; r++) acc[i][j][r] = 0.f;

    float4 pa[8], pv;
#pragma unroll
    for (int p = 0; p < 8; p++)
        pa[p] = *(const float4*)(A + (size_t)(brow + lr + 64 * p) * SDIM + lc);
    pv = *(const float4*)(Vg + (size_t)vr * DH + vc);

    for (int k0 = 0; k0 < SDIM; k0 += KB) {
#pragma unroll
        for (int p = 0; p < 8; p++)
            *(float4*)&As[lr + 64 * p][lc] = tf32x4(pa[p]);
        *(float4*)&Vs[vr][vc] = tf32x4(pv);
        __syncthreads();

        if (k0 + KB < SDIM) {
#pragma unroll
            for (int p = 0; p < 8; p++)
                pa[p] = *(const float4*)(A + (size_t)(brow + lr + 64 * p) * SDIM + k0 + KB + lc);
            pv = *(const float4*)(Vg + (size_t)(k0 + KB + vr) * DH + vc);
        }

#pragma unroll
        for (int ks = 0; ks < 2; ks++) {
            const int kb = ks * 8;
            unsigned a[4][4], b[8][2];
#pragma unroll
            for (int mt = 0; mt < 4; mt++) {
                const int r0 = wid * 64 + mt * 16 + g;
                a[mt][0] = __float_as_uint(As[r0    ][kb + qd]);
                a[mt][1] = __float_as_uint(As[r0 + 8][kb + qd]);
                a[mt][2] = __float_as_uint(As[r0    ][kb + qd + 4]);
                a[mt][3] = __float_as_uint(As[r0 + 8][kb + qd + 4]);
            }
#pragma unroll
            for (int nt = 0; nt < 8; nt++) {
                const int c0 = nt * 8 + g;
                b[nt][0] = __float_as_uint(Vs[kb + qd    ][c0]);
                b[nt][1] = __float_as_uint(Vs[kb + qd + 4][c0]);
            }
#pragma unroll
            for (int mt = 0; mt < 4; mt++)
#pragma unroll
                for (int nt = 0; nt < 8; nt++)
                    mma_tf32(acc[mt][nt], a[mt], b[nt]);
        }
        __syncthreads();
    }

    const int b_ = bh / NH, h = bh % NH;
#pragma unroll
    for (int mt = 0; mt < 4; mt++) {
#pragma unroll
        for (int nt = 0; nt < 8; nt++) {
            const int d = nt * 8 + 2 * qd;
#pragma unroll
            for (int half = 0; half < 2; half++) {
                const int s = brow + wid * 64 + mt * 16 + g + half * 8;
                float2 v;
                v.x = acc[mt][nt][2 * half];
                v.y = acc[mt][nt][2 * half + 1];
                *(float2*)&ctx[((size_t)(b_ * SDIM + s)) * HDIM + h * DH + d] = v;
            }
        }
    }
}

// ---------------------------------------------------------------------------
// In-place masked softmax over last dim of att [B*H*S, S]; warp per row.
// ---------------------------------------------------------------------------
__global__ void __launch_bounds__(256) softmax_rows(
    float* __restrict__ att, const int* __restrict__ mask)
{
    const int wid  = threadIdx.x >> 5;
    const int lane = threadIdx.x & 31;
    const long long row = (long long)blockIdx.x * 8 + wid;

    float* rp = att + (size_t)row * SDIM;
    const int b_ = (int)(row / ((long long)NH * SDIM));
    const int4* mrow = (const int4*)(mask + b_ * SDIM);
    const float4* rp4 = (const float4*)rp;

    float v[64];
    float m = -3.4e38f;
#pragma unroll
    for (int j = 0; j < 16; j++) {
        float4 x = rp4[lane + j * 32];
        int4 mm  = mrow[lane + j * 32];
        if (mm.x == 0) x.x = -1e10f;
        if (mm.y == 0) x.y = -1e10f;
        if (mm.z == 0) x.z = -1e10f;
        if (mm.w == 0) x.w = -1e10f;
        v[4 * j + 0] = x.x; v[4 * j + 1] = x.y;
        v[4 * j + 2] = x.z; v[4 * j + 3] = x.w;
        m = fmaxf(m, fmaxf(fmaxf(x.x, x.y), fmaxf(x.z, x.w)));
    }
#pragma unroll
    for (int o = 16; o > 0; o >>= 1) m = fmaxf(m, __shfl_xor_sync(0xffffffffu, m, o));

    float s = 0.f;
#pragma unroll
    for (int i = 0; i < 64; i++) {
        v[i] = __expf(v[i] - m);
        s += v[i];
    }
#pragma unroll
    for (int o = 16; o > 0; o >>= 1) s += __shfl_xor_sync(0xffffffffu, s, o);
    const float inv = 1.f / s;

    float4* wp4 = (float4*)rp;
#pragma unroll
    for (int j = 0; j < 16; j++) {
        float4 x;
        x.x = v[4 * j + 0] * inv; x.y = v[4 * j + 1] * inv;
        x.z = v[4 * j + 2] * inv; x.w = v[4 * j + 3] * inv;
        wp4[lane + j * 32] = x;
    }
}

// ---------------------------------------------------------------------------
extern "C" void kernel_launch(void* const* d_in, const int* in_sizes, int n_in,
                              void* d_out, int out_size)
{
    const float* query  = (const float*)d_in[0];
    const float* key_in = (const float*)d_in[1];
    const float* value  = (const float*)d_in[2];
    const int*   mask   = (const int*)  d_in[3];
    const float* Wq = (const float*)d_in[4],  *bq = (const float*)d_in[5];
    const float* Wk = (const float*)d_in[6],  *bk = (const float*)d_in[7];
    const float* Wv = (const float*)d_in[8],  *bv = (const float*)d_in[9];
    const float* Wo = (const float*)d_in[10], *bo = (const float*)d_in[11];
    float* out = (float*)d_out;

    float *qbuf, *kbuf, *vbuf, *cbuf;
    cudaGetSymbolAddress((void**)&qbuf, g_Q);
    cudaGetSymbolAddress((void**)&kbuf, g_K);
    cudaGetSymbolAddress((void**)&vbuf, g_V);
    cudaGetSymbolAddress((void**)&cbuf, g_ctx);

    const long long XE = (long long)BDIM * SDIM * HDIM;       // 8,388,608
    float* att = out + XE;                                    // [B,H,S,S]

    // 1) QKV projections (tf32 MMA), scatter to [B,H,S,Dh]
    const dim3 gp(HDIM / NB, (BDIM * SDIM) / MB, 1);
    gemm64<1><<<gp, 256>>>(query,  Wq, bq, qbuf, HDIM, HDIM, 0, 0, 0, 1.f);
    gemm64<1><<<gp, 256>>>(key_in, Wk, bk, kbuf, HDIM, HDIM, 0, 0, 0, 1.f);
    gemm64<1><<<gp, 256>>>(value,  Wv, bv, vbuf, HDIM, HDIM, 0, 0, 0, 1.f);

    // 2) Scores: per (b,h)  E = Q @ K^T / 8   -> att region (energies)
    const long long hd = (long long)SDIM * DH;
    const long long ss = (long long)SDIM * SDIM;
    gemm64<2><<<dim3(SDIM / NB, SDIM / MB, BDIM * NH), 256>>>(
        qbuf, kbuf, nullptr, att, DH, SDIM, hd, hd, ss, 0.125f);

    // 3) Softmax (mask + normalize) in place -> attention probs (2nd output)
    softmax_rows<<<(BDIM * NH * SDIM) / 8, 256>>>(att, mask);

    // 4) PV: ctx[b,s,h*64+d] = P @ V
    gemm_pv64<<<dim3(SDIM / PMB, BDIM * NH), 256>>>(att, cbuf);

    // 5) Output projection -> x (1st output)
    gemm64<0><<<gp, 256>>>(cbuf, Wo, bo, out, HDIM, HDIM, 0, 0, 0, 1.f);
}